// round 3
// baseline (speedup 1.0000x reference)
#include <cuda_runtime.h>

// Problem constants (fixed by the reference: B=2, C=8, L=256, D=128)
#define B_  2
#define C_  8
#define L_  256
#define D_  128
#define TILE 32          // output tile is TILE x TILE per block
#define THREADS 256      // 16x16 threads, each computes 2x2 outputs

__device__ __forceinline__ float tanh_fast(float x) {
    float y;
    asm("tanh.approx.f32 %0, %1;" : "=f"(y) : "f"(x));
    return y;
}

// smem layout (all static, 33,280 B):
//   s_t[D_][TILE]  : start rows for this i-tile, transposed (d-major)
//   e_t[D_][TILE]  : end rows for this j-tile, transposed
//   vv[D_]         : the projection vector
__global__ __launch_bounds__(THREADS)
void Add_Attn_Layer_59055800320841_kernel(const float* __restrict__ S,
                                          const float* __restrict__ E,
                                          const float* __restrict__ V,
                                          float* __restrict__ out) {
    __shared__ float s_t[D_ * TILE];
    __shared__ float e_t[D_ * TILE];
    __shared__ float vv[D_];

    const int bc = blockIdx.z;            // b*C + c   (0..15)
    const int i0 = blockIdx.y * TILE;
    const int j0 = blockIdx.x * TILE;

    const float* Sbase = S + (size_t)bc * L_ * D_ + (size_t)i0 * D_;
    const float* Ebase = E + (size_t)bc * L_ * D_ + (size_t)j0 * D_;

    const int tid = threadIdx.x;

    if (tid < D_) vv[tid] = V[tid];

    // Load + transpose: gmem [row][d] -> smem [d][row].
    // row = idx % TILE so that within a warp `row` varies across lanes:
    // STS bank = row (row-stride 32 floats == 0 mod 32 banks) -> conflict-free.
    #pragma unroll
    for (int idx = tid; idx < TILE * (D_ / 4); idx += THREADS) {
        const int row = idx & (TILE - 1);
        const int d4  = idx >> 5;               // TILE == 32
        const float4 sv = *reinterpret_cast<const float4*>(Sbase + row * D_ + d4 * 4);
        const float4 ev = *reinterpret_cast<const float4*>(Ebase + row * D_ + d4 * 4);
        s_t[(4 * d4 + 0) * TILE + row] = sv.x;
        s_t[(4 * d4 + 1) * TILE + row] = sv.y;
        s_t[(4 * d4 + 2) * TILE + row] = sv.z;
        s_t[(4 * d4 + 3) * TILE + row] = sv.w;
        e_t[(4 * d4 + 0) * TILE + row] = ev.x;
        e_t[(4 * d4 + 1) * TILE + row] = ev.y;
        e_t[(4 * d4 + 2) * TILE + row] = ev.z;
        e_t[(4 * d4 + 3) * TILE + row] = ev.w;
    }
    __syncthreads();

    // Each thread: 2x2 outputs at (i0 + 2*ti + {0,1}, j0 + 2*tj + {0,1})
    const int tj = tid & 15;
    const int ti = tid >> 4;
    const int il = 2 * ti;
    const int jl = 2 * tj;

    float a00 = 0.f, a01 = 0.f, a10 = 0.f, a11 = 0.f;

    #pragma unroll 8
    for (int d = 0; d < D_; d++) {
        const float2 s2 = *reinterpret_cast<const float2*>(&s_t[d * TILE + il]);
        const float2 e2 = *reinterpret_cast<const float2*>(&e_t[d * TILE + jl]);
        const float vd = vv[d];
        a00 = fmaf(vd, tanh_fast(s2.x + e2.x), a00);
        a01 = fmaf(vd, tanh_fast(s2.x + e2.y), a01);
        a10 = fmaf(vd, tanh_fast(s2.y + e2.x), a10);
        a11 = fmaf(vd, tanh_fast(s2.y + e2.y), a11);
    }

    // out[b][i][j][c], c fastest; bc = b*C + c
    const int b = bc >> 3;
    const int c = bc & 7;
    const int i = i0 + il;
    const int j = j0 + jl;
    float* o = out + (((size_t)b * L_ + i) * L_ + j) * C_ + c;
    const size_t row_stride = (size_t)L_ * C_;  // advance i by 1
    o[0]                 = a00;
    o[C_]                = a01;   // j+1
    o[row_stride]        = a10;   // i+1
    o[row_stride + C_]   = a11;   // i+1, j+1
}

extern "C" void kernel_launch(void* const* d_in, const int* in_sizes, int n_in,
                              void* d_out, int out_size) {
    (void)in_sizes; (void)n_in; (void)out_size;
    const float* S = (const float*)d_in[0];   // start_hidden [B,C,L,D]
    const float* E = (const float*)d_in[1];   // end_hidden   [B,C,L,D]
    const float* V = (const float*)d_in[2];   // v [D]
    float* out = (float*)d_out;               // [B,L,L,C] float32

    dim3 grid(L_ / TILE, L_ / TILE, B_ * C_); // (8, 8, 16) = 1024 blocks
    Add_Attn_Layer_59055800320841_kernel<<<grid, THREADS>>>(S, E, V, out);
}

// round 4
// speedup vs baseline: 1.0307x; 1.0307x over previous
#include <cuda_runtime.h>

// Problem constants (fixed by the reference: B=2, C=8, L=256, D=128)
#define B_  2
#define C_  8
#define L_  256
#define D_  128
#define TILE 32          // output tile is TILE x TILE per block
#define THREADS 256      // 16x16 threads, each computes 2x2 outputs

__device__ __forceinline__ float tanh_fast(float x) {
    float y;
    asm("tanh.approx.f32 %0, %1;" : "=f"(y) : "f"(x));
    return y;
}

// smem layout: paired-d interleave so one LDS.128 feeds 2 d-values for a
// row-pair:
//   sP[d2*64 + (row&~1)*2 + (d&1)*2 + (row&1)]  holds s(d, row), d2 = d>>1
// i.e. 16B word at (d2*64 + il*2) = { s(2d2,il), s(2d2,il+1),
//                                     s(2d2+1,il), s(2d2+1,il+1) }
__global__ __launch_bounds__(THREADS)
void Add_Attn_Layer_59055800320841_kernel(const float* __restrict__ S,
                                          const float* __restrict__ E,
                                          const float* __restrict__ V,
                                          float* __restrict__ out) {
    __shared__ float sP[(D_ / 2) * (TILE * 2)];   // 64 * 64 floats = 16 KB
    __shared__ float eP[(D_ / 2) * (TILE * 2)];   // 16 KB
    __shared__ float vv[D_];

    const int bc = blockIdx.z;            // b*C + c   (0..15)
    const int i0 = blockIdx.y * TILE;
    const int j0 = blockIdx.x * TILE;

    const float* Sbase = S + (size_t)bc * L_ * D_ + (size_t)i0 * D_;
    const float* Ebase = E + (size_t)bc * L_ * D_ + (size_t)j0 * D_;

    const int tid = threadIdx.x;

    if (tid < D_) vv[tid] = V[tid];

    // Load + transpose into paired-d interleaved layout.
    // idx enumerates (row, d4) with row fastest so GMEM float4 loads coalesce
    // across d within a row... (row in lanes -> each lane a different row,
    // same d4: fully coalesced 16B per lane on a 128B-aligned row stride).
    #pragma unroll
    for (int idx = tid; idx < TILE * (D_ / 4); idx += THREADS) {
        const int row = idx & (TILE - 1);
        const int d4  = idx >> 5;                  // 0..31, d = 4*d4 + q
        const float4 sv = *reinterpret_cast<const float4*>(Sbase + row * D_ + d4 * 4);
        const float4 ev = *reinterpret_cast<const float4*>(Ebase + row * D_ + d4 * 4);
        const int r2 = ((row & ~1) << 1) + (row & 1);
        const int b0 = (2 * d4) * (TILE * 2) + r2;       // d = 4d4+0 / +1
        const int b1 = (2 * d4 + 1) * (TILE * 2) + r2;   // d = 4d4+2 / +3
        sP[b0]     = sv.x;
        sP[b0 + 2] = sv.y;
        sP[b1]     = sv.z;
        sP[b1 + 2] = sv.w;
        eP[b0]     = ev.x;
        eP[b0 + 2] = ev.y;
        eP[b1]     = ev.z;
        eP[b1 + 2] = ev.w;
    }
    __syncthreads();

    // Each thread: 2x2 outputs at (i0 + 2*ti + {0,1}, j0 + 2*tj + {0,1})
    const int tj = tid & 15;
    const int ti = tid >> 4;
    const int il = 2 * ti;
    const int jl = 2 * tj;

    float a00 = 0.f, a01 = 0.f, a10 = 0.f, a11 = 0.f;

    const float* sp = sP + il * 2;   // 16B aligned (il even)
    const float* ep = eP + jl * 2;

    #pragma unroll 4
    for (int d2 = 0; d2 < D_ / 2; d2++) {
        const float4 s4 = *reinterpret_cast<const float4*>(sp + d2 * (TILE * 2));
        const float4 e4 = *reinterpret_cast<const float4*>(ep + d2 * (TILE * 2));
        const float2 v2 = *reinterpret_cast<const float2*>(vv + 2 * d2);
        // d = 2*d2 (even): rows in .x/.y, cols in .x/.y
        a00 = fmaf(v2.x, tanh_fast(s4.x + e4.x), a00);
        a01 = fmaf(v2.x, tanh_fast(s4.x + e4.y), a01);
        a10 = fmaf(v2.x, tanh_fast(s4.y + e4.x), a10);
        a11 = fmaf(v2.x, tanh_fast(s4.y + e4.y), a11);
        // d = 2*d2+1 (odd): rows in .z/.w, cols in .z/.w
        a00 = fmaf(v2.y, tanh_fast(s4.z + e4.z), a00);
        a01 = fmaf(v2.y, tanh_fast(s4.z + e4.w), a01);
        a10 = fmaf(v2.y, tanh_fast(s4.w + e4.z), a10);
        a11 = fmaf(v2.y, tanh_fast(s4.w + e4.w), a11);
    }

    // out[b][i][j][c], c fastest; bc = b*C + c
    const int b = bc >> 3;
    const int c = bc & 7;
    const int i = i0 + il;
    const int j = j0 + jl;
    float* o = out + (((size_t)b * L_ + i) * L_ + j) * C_ + c;
    const size_t row_stride = (size_t)L_ * C_;  // advance i by 1
    o[0]                 = a00;
    o[C_]                = a01;   // j+1
    o[row_stride]        = a10;   // i+1
    o[row_stride + C_]   = a11;   // i+1, j+1
}

extern "C" void kernel_launch(void* const* d_in, const int* in_sizes, int n_in,
                              void* d_out, int out_size) {
    (void)in_sizes; (void)n_in; (void)out_size;
    const float* S = (const float*)d_in[0];   // start_hidden [B,C,L,D]
    const float* E = (const float*)d_in[1];   // end_hidden   [B,C,L,D]
    const float* V = (const float*)d_in[2];   // v [D]
    float* out = (float*)d_out;               // [B,L,L,C] float32

    dim3 grid(L_ / TILE, L_ / TILE, B_ * C_); // (8, 8, 16) = 1024 blocks
    Add_Attn_Layer_59055800320841_kernel<<<grid, THREADS>>>(S, E, V, out);
}